// round 1
// baseline (speedup 1.0000x reference)
#include <cuda_runtime.h>

#define NN 8192
#define FIN 512
#define FOUT 256

// Scratch (device globals — no allocation allowed)
__device__ float g_h[NN * FOUT];                // h = x @ W
__device__ float g_A[NN], g_B[NN];              // exp(f), exp(0.2 f)  (row factors)
__device__ float g_E[NN], g_F[NN];              // exp(g), exp(0.2 g)  (col factors)
__device__ float g_G[NN], g_T[NN];              // g_j, threshold t_i = -f_i

// Packed dual-FMA (sm_100+): 2 fp32 MACs per instruction (rt=1 vs rt=2 for FFMA)
static __device__ __forceinline__ float2 ffma2(float2 a, float2 b, float2 c) {
    unsigned long long A = *reinterpret_cast<unsigned long long*>(&a);
    unsigned long long B = *reinterpret_cast<unsigned long long*>(&b);
    unsigned long long C = *reinterpret_cast<unsigned long long*>(&c);
    unsigned long long D;
    asm("fma.rn.f32x2 %0, %1, %2, %3;" : "=l"(D) : "l"(A), "l"(B), "l"(C));
    return *reinterpret_cast<float2*>(&D);
}

// ---------------------------------------------------------------------------
// Kernel 1: h = x @ W.  [8192,512]@[512,256].
// 32 rows per CTA, 256 threads = one output column each, f32x2 accumulators.
// W (512 KB) stays in L2; x tiles staged in SMEM transposed + i-packed.
// ---------------------------------------------------------------------------
__global__ void __launch_bounds__(256) k_xw(const float* __restrict__ x,
                                            const float* __restrict__ W) {
    __shared__ __align__(16) float x_s[64][36];   // [kk][i], stride 144B (16B aligned)
    const int tid = threadIdx.x;
    const int i0  = blockIdx.x * 32;
    const int c   = tid;
    const int r   = tid >> 3;          // 0..31 row within block
    const int kq  = (tid & 7) * 8;     // 8 k's per thread

    float2 acc[16];
#pragma unroll
    for (int q = 0; q < 16; q++) acc[q] = make_float2(0.f, 0.f);

    for (int k0 = 0; k0 < FIN; k0 += 64) {
        float4 v0 = *reinterpret_cast<const float4*>(&x[(i0 + r) * FIN + k0 + kq]);
        float4 v1 = *reinterpret_cast<const float4*>(&x[(i0 + r) * FIN + k0 + kq + 4]);
        __syncthreads();   // prior tile's readers done before overwrite
        x_s[kq + 0][r] = v0.x; x_s[kq + 1][r] = v0.y;
        x_s[kq + 2][r] = v0.z; x_s[kq + 3][r] = v0.w;
        x_s[kq + 4][r] = v1.x; x_s[kq + 5][r] = v1.y;
        x_s[kq + 6][r] = v1.z; x_s[kq + 7][r] = v1.w;
        __syncthreads();

        const float* wp = W + k0 * FOUT + c;
#pragma unroll 4
        for (int kk = 0; kk < 64; kk++) {
            float wv = wp[kk * FOUT];
            float2 wv2 = make_float2(wv, wv);
#pragma unroll
            for (int q = 0; q < 8; q++) {
                float4 pq = *reinterpret_cast<const float4*>(&x_s[kk][q * 4]);
                acc[2 * q]     = ffma2(make_float2(pq.x, pq.y), wv2, acc[2 * q]);
                acc[2 * q + 1] = ffma2(make_float2(pq.z, pq.w), wv2, acc[2 * q + 1]);
            }
        }
    }
#pragma unroll
    for (int q = 0; q < 16; q++) {
        g_h[(i0 + 2 * q) * FOUT + c]     = acc[q].x;
        g_h[(i0 + 2 * q + 1) * FOUT + c] = acc[q].y;
    }
}

// ---------------------------------------------------------------------------
// Kernel 2: f_i = h_i . a[0:256], g_i = h_i . a[256:512]; store exp factors.
// One warp per row. O(N) exps instead of O(N^2).
// ---------------------------------------------------------------------------
__global__ void __launch_bounds__(256) k_scores(const float* __restrict__ a) {
    const int w    = threadIdx.x >> 5;
    const int lane = threadIdx.x & 31;
    const int i    = blockIdx.x * 8 + w;

    float f = 0.f, g = 0.f;
#pragma unroll
    for (int q = 0; q < 8; q++) {
        int cidx = lane + q * 32;
        float hv = g_h[i * FOUT + cidx];
        f += hv * a[cidx];
        g += hv * a[FOUT + cidx];
    }
#pragma unroll
    for (int off = 16; off; off >>= 1) {
        f += __shfl_down_sync(0xffffffffu, f, off);
        g += __shfl_down_sync(0xffffffffu, g, off);
    }
    if (lane == 0) {
        g_A[i] = expf(f);        g_B[i] = expf(0.2f * f);
        g_E[i] = expf(g);        g_F[i] = expf(0.2f * g);
        g_G[i] = g;              g_T[i] = -f;
    }
}

// ---------------------------------------------------------------------------
// Kernel 3: fused masked softmax + aggregation.
//   p_ij = adj ? (g_j > -f_i ? A_i*E_j : B_i*F_j) : 0     (no exp per pair!)
//   out_i = (sum_j p_ij h_j) / (sum_j p_ij)
// 32 rows per CTA (rows owned fully -> Z local), 256 threads = 1 column each.
// p tiles [64 j][32 i] in SMEM, i-contiguous for float4 loads feeding f32x2.
// h read straight from L2 (8 MB, resident, reused 256x).
// ---------------------------------------------------------------------------
__global__ void __launch_bounds__(256) k_attn(const int* __restrict__ adj,
                                              float* __restrict__ out) {
    __shared__ __align__(16) float p_s[64][36];
    __shared__ float E_s[64], F_s[64], G_s[64];
    __shared__ float A_s[32], B_s[32], T_s[32];
    __shared__ float rowZ[32];

    const int tid = threadIdx.x;
    const int i0  = blockIdx.x * 32;
    const int c   = tid;
    const int r   = tid >> 3;          // row for adj/p phase
    const int jq  = (tid & 7) * 8;     // 8 j's per thread

    if (tid < 32) {
        A_s[tid] = g_A[i0 + tid];
        B_s[tid] = g_B[i0 + tid];
        T_s[tid] = g_T[i0 + tid];
        rowZ[tid] = 0.f;
    }
    float2 acc[16];
#pragma unroll
    for (int q = 0; q < 16; q++) acc[q] = make_float2(0.f, 0.f);
    __syncthreads();

    for (int j0 = 0; j0 < NN; j0 += 64) {
        // issue adjacency loads early (DRAM latency overlap)
        const int* ap = adj + (i0 + r) * NN + j0 + jq;
        int4 a0 = *reinterpret_cast<const int4*>(ap);
        int4 a1 = *reinterpret_cast<const int4*>(ap + 4);
        if (tid < 64) {
            E_s[tid] = g_E[j0 + tid];
            F_s[tid] = g_F[j0 + tid];
            G_s[tid] = g_G[j0 + tid];
        }
        __syncthreads();

        const float Ar = A_s[r], Br = B_s[r], Tr = T_s[r];
        float z = 0.f;
        int av[8] = {a0.x, a0.y, a0.z, a0.w, a1.x, a1.y, a1.z, a1.w};
#pragma unroll
        for (int u = 0; u < 8; u++) {
            int jj = jq + u;
            float p = 0.f;
            if (av[u] > 0)
                p = (G_s[jj] > Tr) ? Ar * E_s[jj] : Br * F_s[jj];
            z += p;
            p_s[jj][r] = p;
        }
        atomicAdd(&rowZ[r], z);
        __syncthreads();

        // MAC phase: acc[rows] += p[rows][jj] * h[jj][c]
        const float* hp = g_h + j0 * FOUT + c;
#pragma unroll 2
        for (int jj = 0; jj < 64; jj += 4) {
            float h0 = hp[0];
            float h1 = hp[FOUT];
            float h2 = hp[2 * FOUT];
            float h3 = hp[3 * FOUT];
            hp += 4 * FOUT;
#pragma unroll
            for (int d = 0; d < 4; d++) {
                float hv = (d == 0) ? h0 : (d == 1) ? h1 : (d == 2) ? h2 : h3;
                float2 hv2 = make_float2(hv, hv);
#pragma unroll
                for (int q = 0; q < 8; q++) {
                    float4 pq = *reinterpret_cast<const float4*>(&p_s[jj + d][q * 4]);
                    acc[2 * q]     = ffma2(make_float2(pq.x, pq.y), hv2, acc[2 * q]);
                    acc[2 * q + 1] = ffma2(make_float2(pq.z, pq.w), hv2, acc[2 * q + 1]);
                }
            }
        }
        __syncthreads();
    }

    // normalize and write
#pragma unroll
    for (int q = 0; q < 16; q++) {
        out[(i0 + 2 * q) * FOUT + c]     = acc[q].x / rowZ[2 * q];
        out[(i0 + 2 * q + 1) * FOUT + c] = acc[q].y / rowZ[2 * q + 1];
    }
}

// ---------------------------------------------------------------------------
extern "C" void kernel_launch(void* const* d_in, const int* in_sizes, int n_in,
                              void* d_out, int out_size) {
    const float* x   = (const float*)d_in[0];   // [8192, 512]
    const int*   adj = (const int*)  d_in[1];   // [8192, 8192]
    const float* W   = (const float*)d_in[2];   // [512, 256]
    const float* a   = (const float*)d_in[3];   // [512, 1]
    float* out = (float*)d_out;                 // [8192, 256]

    k_xw<<<NN / 32, 256>>>(x, W);
    k_scores<<<NN / 8, 256>>>(a);
    k_attn<<<NN / 32, 256>>>(adj, out);
}

// round 3
// speedup vs baseline: 1.4680x; 1.4680x over previous
#include <cuda_runtime.h>
#include <cstdint>

#define NN 8192
#define FIN 512
#define FOUT 256
#define CH 32
#define NCH (NN / CH)
#define CTA_M 64

// ---------------- scratch (device globals; no allocation allowed) -----------
__device__ float  g_h [(size_t)NN * FOUT];    // h = x@W, fp32 exact (for scores)
__device__ float  g_hT[(size_t)FOUT * NN];    // h^T, tf32-rounded (MMA B operand)
__device__ float4 g_EFG[NN];                  // per-j: (E=e^g, F=e^{0.2g}, G=g, 0)
__device__ float4 g_ABT[NN];                  // per-i: (A=e^f, B=e^{0.2f}, T=-f, 0)

// ---------------- helpers ----------------------------------------------------
static __device__ __forceinline__ float2 ffma2(float2 a, float2 b, float2 c) {
    unsigned long long A = *reinterpret_cast<unsigned long long*>(&a);
    unsigned long long B = *reinterpret_cast<unsigned long long*>(&b);
    unsigned long long C = *reinterpret_cast<unsigned long long*>(&c);
    unsigned long long D;
    asm("fma.rn.f32x2 %0, %1, %2, %3;" : "=l"(D) : "l"(A), "l"(B), "l"(C));
    return *reinterpret_cast<float2*>(&D);
}

static __device__ __forceinline__ float tf32r(float x) {   // round-to-nearest tf32
    uint32_t r;
    asm("cvt.rna.tf32.f32 %0, %1;" : "=r"(r) : "f"(x));
    return __uint_as_float(r);
}

// d += A(16x8) * B(8x8), tf32 inputs / f32 accum. Portable since sm_80.
static __device__ __forceinline__ void mma16n8k8(float* d, const uint32_t* a,
                                                 const uint32_t* b) {
    asm volatile(
        "mma.sync.aligned.m16n8k8.row.col.f32.tf32.tf32.f32 "
        "{%0,%1,%2,%3}, {%4,%5,%6,%7}, {%8,%9}, {%0,%1,%2,%3};"
        : "+f"(d[0]), "+f"(d[1]), "+f"(d[2]), "+f"(d[3])
        : "r"(a[0]), "r"(a[1]), "r"(a[2]), "r"(a[3]), "r"(b[0]), "r"(b[1]));
}

// ---------------------------------------------------------------------------
// Kernel 1: h = x @ W (fp32 f32x2). Writes g_h (exact) and g_hT (tf32, transposed).
// ---------------------------------------------------------------------------
__global__ void __launch_bounds__(256) k_xw(const float* __restrict__ x,
                                            const float* __restrict__ W) {
    __shared__ __align__(16) float x_s[64][36];
    const int tid = threadIdx.x;
    const int i0  = blockIdx.x * 32;
    const int c   = tid;
    const int r   = tid >> 3;
    const int kq  = (tid & 7) * 8;

    float2 acc[16];
#pragma unroll
    for (int q = 0; q < 16; q++) acc[q] = make_float2(0.f, 0.f);

    for (int k0 = 0; k0 < FIN; k0 += 64) {
        float4 v0 = *reinterpret_cast<const float4*>(&x[(i0 + r) * FIN + k0 + kq]);
        float4 v1 = *reinterpret_cast<const float4*>(&x[(i0 + r) * FIN + k0 + kq + 4]);
        __syncthreads();
        x_s[kq + 0][r] = v0.x; x_s[kq + 1][r] = v0.y;
        x_s[kq + 2][r] = v0.z; x_s[kq + 3][r] = v0.w;
        x_s[kq + 4][r] = v1.x; x_s[kq + 5][r] = v1.y;
        x_s[kq + 6][r] = v1.z; x_s[kq + 7][r] = v1.w;
        __syncthreads();

        const float* wp = W + k0 * FOUT + c;
#pragma unroll 4
        for (int kk = 0; kk < 64; kk++) {
            float wv = wp[kk * FOUT];
            float2 wv2 = make_float2(wv, wv);
#pragma unroll
            for (int q = 0; q < 8; q++) {
                float4 pq = *reinterpret_cast<const float4*>(&x_s[kk][q * 4]);
                acc[2 * q]     = ffma2(make_float2(pq.x, pq.y), wv2, acc[2 * q]);
                acc[2 * q + 1] = ffma2(make_float2(pq.z, pq.w), wv2, acc[2 * q + 1]);
            }
        }
    }
    float rv[32];
#pragma unroll
    for (int q = 0; q < 16; q++) {
        g_h[(size_t)(i0 + 2 * q) * FOUT + c]     = acc[q].x;
        g_h[(size_t)(i0 + 2 * q + 1) * FOUT + c] = acc[q].y;
        rv[2 * q] = acc[q].x; rv[2 * q + 1] = acc[q].y;
    }
    float* ht = g_hT + (size_t)c * NN + i0;
#pragma unroll
    for (int q = 0; q < 8; q++) {
        *reinterpret_cast<float4*>(ht + 4 * q) =
            make_float4(tf32r(rv[4 * q]), tf32r(rv[4 * q + 1]),
                        tf32r(rv[4 * q + 2]), tf32r(rv[4 * q + 3]));
    }
}

// ---------------------------------------------------------------------------
// Kernel 2: scores f,g per node -> exp factors (O(N) exps total).
// ---------------------------------------------------------------------------
__global__ void __launch_bounds__(256) k_scores(const float* __restrict__ a) {
    const int w    = threadIdx.x >> 5;
    const int lane = threadIdx.x & 31;
    const int i    = blockIdx.x * 8 + w;

    float f = 0.f, g = 0.f;
#pragma unroll
    for (int q = 0; q < 8; q++) {
        int cidx = lane + q * 32;
        float hv = g_h[(size_t)i * FOUT + cidx];
        f += hv * a[cidx];
        g += hv * a[FOUT + cidx];
    }
#pragma unroll
    for (int off = 16; off; off >>= 1) {
        f += __shfl_down_sync(0xffffffffu, f, off);
        g += __shfl_down_sync(0xffffffffu, g, off);
    }
    if (lane == 0) {
        g_EFG[i] = make_float4(expf(g), expf(0.2f * g), g, 0.f);
        g_ABT[i] = make_float4(expf(f), expf(0.2f * f), -f, 0.f);
    }
}

// ---------------------------------------------------------------------------
// Kernel 3: mma.sync tf32 fused masked-softmax aggregation.
// CTA: 64 rows x 256 cols, 8 warps (2m x 4n), warp tile 32x64.
// Per chunk (K=32 j's): P[64,32] generated in SMEM (no per-pair exp),
// hT[256,32] staged in SMEM, 64 mma per warp.
// ---------------------------------------------------------------------------
__global__ void __launch_bounds__(256, 1) k_attn_mma(const int* __restrict__ adj,
                                                     float* __restrict__ out) {
    __shared__ __align__(16) float A_s[CTA_M][36];    // P tile (tf32)
    __shared__ __align__(16) float B_s[FOUT][36];     // hT tile (tf32)
    __shared__ __align__(16) float4 EFG_s[2][CH];     // double-buffered j factors
    __shared__ float zs[256];
    __shared__ float rowZ[CTA_M];

    const int tid  = threadIdx.x;
    const int lane = tid & 31;
    const int wid  = tid >> 5;
    const int wm   = wid >> 2;          // 0..1 : 32-row slab
    const int wn   = wid & 3;           // 0..3 : 64-col slab
    const int i0   = blockIdx.x * CTA_M;

    const int pr = tid >> 2;            // P-gen: row 0..63
    const int kq = (tid & 3) * 8;       // P-gen: 8 j's

    const float4 abt = g_ABT[i0 + pr];
    const float Ai = abt.x, Bi = abt.y, Ti = abt.z;
    float zacc = 0.f;

    float acc[2][8][4];
#pragma unroll
    for (int mt = 0; mt < 2; mt++)
#pragma unroll
        for (int nt = 0; nt < 8; nt++)
#pragma unroll
            for (int q = 0; q < 4; q++) acc[mt][nt][q] = 0.f;

    // prologue: EFG for chunk 0, adj for chunk 0
    if (tid < CH) EFG_s[0][tid] = g_EFG[tid];
    const int4* arow = reinterpret_cast<const int4*>(adj + (size_t)(i0 + pr) * NN);
    int4 av0 = arow[kq >> 2];
    int4 av1 = arow[(kq >> 2) + 1];
    __syncthreads();

    for (int c = 0; c < NCH; c++) {
        const int j0 = c * CH;

        // ---- stage phase ----
        // B tile: thread = feature row, 32 j's
        {
            const float4* src = reinterpret_cast<const float4*>(g_hT + (size_t)tid * NN + j0);
            float4 b0 = src[0], b1 = src[1], b2 = src[2], b3 = src[3];
            float4 b4 = src[4], b5 = src[5], b6 = src[6], b7 = src[7];
            float4* bd = reinterpret_cast<float4*>(&B_s[tid][0]);
            bd[0] = b0; bd[1] = b1; bd[2] = b2; bd[3] = b3;
            bd[4] = b4; bd[5] = b5; bd[6] = b6; bd[7] = b7;
        }
        // EFG for next chunk (other buffer)
        if (tid < CH && c + 1 < NCH) EFG_s[(c + 1) & 1][tid] = g_EFG[j0 + CH + tid];

        // P tile from prefetched adj + this chunk's EFG
        {
            const float4* eb = EFG_s[c & 1];
            int avv[8] = {av0.x, av0.y, av0.z, av0.w, av1.x, av1.y, av1.z, av1.w};
            float pv[8];
#pragma unroll
            for (int u = 0; u < 8; u++) {
                float4 e = eb[kq + u];
                float p = (e.z > Ti) ? Ai * e.x : Bi * e.y;
                p = (avv[u] > 0) ? p : 0.f;
                zacc += p;
                pv[u] = tf32r(p);
            }
            float4* ad = reinterpret_cast<float4*>(&A_s[pr][kq]);
            ad[0] = make_float4(pv[0], pv[1], pv[2], pv[3]);
            ad[1] = make_float4(pv[4], pv[5], pv[6], pv[7]);
        }
        // prefetch adj for next chunk
        if (c + 1 < NCH) {
            const int jn = (j0 + CH + kq) >> 2;
            av0 = arow[jn];
            av1 = arow[jn + 1];
        }
        __syncthreads();   // tiles visible

        // ---- mma phase ----
#pragma unroll
        for (int ks = 0; ks < 4; ks++) {
            const int k0 = ks * 8;
            uint32_t af[2][4];
#pragma unroll
            for (int mt = 0; mt < 2; mt++) {
                const int r = wm * 32 + mt * 16 + (lane >> 2);
                af[mt][0] = __float_as_uint(A_s[r][k0 + (lane & 3)]);
                af[mt][1] = __float_as_uint(A_s[r + 8][k0 + (lane & 3)]);
                af[mt][2] = __float_as_uint(A_s[r][k0 + (lane & 3) + 4]);
                af[mt][3] = __float_as_uint(A_s[r + 8][k0 + (lane & 3) + 4]);
            }
#pragma unroll
            for (int nt = 0; nt < 8; nt++) {
                const int n = wn * 64 + nt * 8 + (lane >> 2);
                uint32_t bf[2];
                bf[0] = __float_as_uint(B_s[n][k0 + (lane & 3)]);
                bf[1] = __float_as_uint(B_s[n][k0 + (lane & 3) + 4]);
                mma16n8k8(acc[0][nt], af[0], bf);
                mma16n8k8(acc[1][nt], af[1], bf);
            }
        }
        __syncthreads();   // mma reads done before next staging
    }

    // ---- row-sum reduction ----
    zs[tid] = zacc;
    __syncthreads();
    if (tid < CTA_M)
        rowZ[tid] = zs[4 * tid] + zs[4 * tid + 1] + zs[4 * tid + 2] + zs[4 * tid + 3];
    __syncthreads();

    // ---- epilogue: normalize + store ----
#pragma unroll
    for (int mt = 0; mt < 2; mt++) {
        const int rca = wm * 32 + mt * 16 + (lane >> 2);
        const float inv0 = 1.0f / rowZ[rca];
        const float inv1 = 1.0f / rowZ[rca + 8];
        float* o0 = out + (size_t)(i0 + rca) * FOUT;
        float* o1 = out + (size_t)(i0 + rca + 8) * FOUT;
#pragma unroll
        for (int nt = 0; nt < 8; nt++) {
            const int colb = wn * 64 + nt * 8 + 2 * (lane & 3);
            *reinterpret_cast<float2*>(o0 + colb) =
                make_float2(acc[mt][nt][0] * inv0, acc[mt][nt][1] * inv0);
            *reinterpret_cast<float2*>(o1 + colb) =
                make_float2(acc[mt][nt][2] * inv1, acc[mt][nt][3] * inv1);
        }
    }
}

// ---------------------------------------------------------------------------
extern "C" void kernel_launch(void* const* d_in, const int* in_sizes, int n_in,
                              void* d_out, int out_size) {
    const float* x   = (const float*)d_in[0];
    const int*   adj = (const int*)  d_in[1];
    const float* W   = (const float*)d_in[2];
    const float* a   = (const float*)d_in[3];
    float* out = (float*)d_out;

    k_xw<<<NN / 32, 256>>>(x, W);
    k_scores<<<NN / 8, 256>>>(a);
    k_attn_mma<<<NN / CTA_M, 256>>>(adj, out);
}

// round 5
// speedup vs baseline: 2.4369x; 1.6600x over previous
#include <cuda_runtime.h>
#include <cuda_fp16.h>
#include <cstdint>

#define NN 8192
#define FIN 512
#define FOUT 256
#define CH 32
#define NCH (NN / CH)
#define CTA_M 64
#define BSTRIDE 40   // halves per row (80B): conflict-free ldmatrix phases

// ---------------- scratch (device globals; no allocation allowed) -----------
__device__ float   g_h   [(size_t)NN * FOUT];   // h = x@W fp32 (scores)
__device__ __half  g_hT16[(size_t)FOUT * NN];   // h^T fp16 (MMA B operand)
__device__ float4  g_EFG[NN];                   // per-j: (E=e^g, F=e^{0.2g}, G=g, 0)
__device__ float2  g_RT [NN];                   // per-i: (R=e^{-0.8f}, T=-f)

// ---------------- helpers ----------------------------------------------------
static __device__ __forceinline__ float2 ffma2(float2 a, float2 b, float2 c) {
    unsigned long long A = *reinterpret_cast<unsigned long long*>(&a);
    unsigned long long B = *reinterpret_cast<unsigned long long*>(&b);
    unsigned long long C = *reinterpret_cast<unsigned long long*>(&c);
    unsigned long long D;
    asm("fma.rn.f32x2 %0, %1, %2, %3;" : "=l"(D) : "l"(A), "l"(B), "l"(C));
    return *reinterpret_cast<float2*>(&D);
}

static __device__ __forceinline__ uint32_t smem_u32(const void* p) {
    uint32_t a;
    asm("{ .reg .u64 t; cvta.to.shared.u64 t, %1; cvt.u32.u64 %0, t; }" : "=r"(a) : "l"(p));
    return a;
}

static __device__ __forceinline__ void cp16(uint32_t dst, const void* src) {
    asm volatile("cp.async.ca.shared.global [%0], [%1], 16;" :: "r"(dst), "l"(src));
}
static __device__ __forceinline__ void cp_commit() {
    asm volatile("cp.async.commit_group;");
}
static __device__ __forceinline__ void cp_wait_all() {
    asm volatile("cp.async.wait_group 0;");
}

static __device__ __forceinline__ void ldsm4(uint32_t* r, uint32_t addr) {
    asm volatile("ldmatrix.sync.aligned.m8n8.x4.shared.b16 {%0,%1,%2,%3}, [%4];"
                 : "=r"(r[0]), "=r"(r[1]), "=r"(r[2]), "=r"(r[3]) : "r"(addr));
}

// d += A(16x16) * B(16x8), fp16 inputs / f32 accumulate
static __device__ __forceinline__ void mma16816(float* d, const uint32_t* a,
                                                uint32_t b0, uint32_t b1) {
    asm volatile(
        "mma.sync.aligned.m16n8k16.row.col.f32.f16.f16.f32 "
        "{%0,%1,%2,%3}, {%4,%5,%6,%7}, {%8,%9}, {%0,%1,%2,%3};"
        : "+f"(d[0]), "+f"(d[1]), "+f"(d[2]), "+f"(d[3])
        : "r"(a[0]), "r"(a[1]), "r"(a[2]), "r"(a[3]), "r"(b0), "r"(b1));
}

// ---------------------------------------------------------------------------
// Kernel 1: h = x @ W (fp32 f32x2). Writes g_h (fp32) and g_hT16 (fp16, transposed).
// ---------------------------------------------------------------------------
__global__ void __launch_bounds__(256) k_xw(const float* __restrict__ x,
                                            const float* __restrict__ W) {
    __shared__ __align__(16) float x_s[64][36];
    const int tid = threadIdx.x;
    const int i0  = blockIdx.x * 32;
    const int c   = tid;
    const int r   = tid >> 3;
    const int kq  = (tid & 7) * 8;

    float2 acc[16];
#pragma unroll
    for (int q = 0; q < 16; q++) acc[q] = make_float2(0.f, 0.f);

    for (int k0 = 0; k0 < FIN; k0 += 64) {
        float4 v0 = *reinterpret_cast<const float4*>(&x[(i0 + r) * FIN + k0 + kq]);
        float4 v1 = *reinterpret_cast<const float4*>(&x[(i0 + r) * FIN + k0 + kq + 4]);
        __syncthreads();
        x_s[kq + 0][r] = v0.x; x_s[kq + 1][r] = v0.y;
        x_s[kq + 2][r] = v0.z; x_s[kq + 3][r] = v0.w;
        x_s[kq + 4][r] = v1.x; x_s[kq + 5][r] = v1.y;
        x_s[kq + 6][r] = v1.z; x_s[kq + 7][r] = v1.w;
        __syncthreads();

        const float* wp = W + k0 * FOUT + c;
#pragma unroll 4
        for (int kk = 0; kk < 64; kk++) {
            float wv = wp[kk * FOUT];
            float2 wv2 = make_float2(wv, wv);
#pragma unroll
            for (int q = 0; q < 8; q++) {
                float4 pq = *reinterpret_cast<const float4*>(&x_s[kk][q * 4]);
                acc[2 * q]     = ffma2(make_float2(pq.x, pq.y), wv2, acc[2 * q]);
                acc[2 * q + 1] = ffma2(make_float2(pq.z, pq.w), wv2, acc[2 * q + 1]);
            }
        }
    }
    float rv[32];
#pragma unroll
    for (int q = 0; q < 16; q++) {
        g_h[(size_t)(i0 + 2 * q) * FOUT + c]     = acc[q].x;
        g_h[(size_t)(i0 + 2 * q + 1) * FOUT + c] = acc[q].y;
        rv[2 * q] = acc[q].x; rv[2 * q + 1] = acc[q].y;
    }
    __half* ht = g_hT16 + (size_t)c * NN + i0;
#pragma unroll
    for (int q = 0; q < 4; q++) {
        __half2 h2[4];
#pragma unroll
        for (int u = 0; u < 4; u++)
            h2[u] = __floats2half2_rn(rv[8 * q + 2 * u], rv[8 * q + 2 * u + 1]);
        *reinterpret_cast<uint4*>(ht + 8 * q) = *reinterpret_cast<uint4*>(h2);
    }
}

// ---------------------------------------------------------------------------
// Kernel 2: per-node scores -> exp factors (O(N) exps total).
// ---------------------------------------------------------------------------
__global__ void __launch_bounds__(256) k_scores(const float* __restrict__ a) {
    const int w    = threadIdx.x >> 5;
    const int lane = threadIdx.x & 31;
    const int i    = blockIdx.x * 8 + w;

    float f = 0.f, g = 0.f;
#pragma unroll
    for (int q = 0; q < 8; q++) {
        int cidx = lane + q * 32;
        float hv = g_h[(size_t)i * FOUT + cidx];
        f += hv * a[cidx];
        g += hv * a[FOUT + cidx];
    }
#pragma unroll
    for (int off = 16; off; off >>= 1) {
        f += __shfl_down_sync(0xffffffffu, f, off);
        g += __shfl_down_sync(0xffffffffu, g, off);
    }
    if (lane == 0) {
        g_EFG[i] = make_float4(expf(g), expf(0.2f * g), g, 0.f);
        g_RT[i]  = make_float2(expf(-0.8f * f), -f);   // row-rescaled branch factor
    }
}

// ---------------------------------------------------------------------------
// Kernel 3: fp16 mma.sync fused masked-softmax aggregation.
// Row-rescaled p' = adj ? (G_j > T_i ? E_j : R_i*F_j) : 0  (scale cancels in softmax)
// CTA: 64 rows x 256 cols, 8 warps (2m x 4n). cp.async double-buffered B/EFG,
// ldmatrix fragment loads, fp16 m16n8k16 with fp32 accum.
// ---------------------------------------------------------------------------
__global__ void __launch_bounds__(256) k_attn_f16(const int* __restrict__ adj,
                                                  float* __restrict__ out) {
    __shared__ __align__(16) __half A_s[CTA_M][BSTRIDE];      // P tile
    __shared__ __align__(16) __half B_s[2][FOUT][BSTRIDE];    // hT tiles (dbl buf)
    __shared__ __align__(16) float4 EFG_s[2][CH];
    __shared__ float zs[256];
    __shared__ float rowZ[CTA_M];

    const int tid  = threadIdx.x;
    const int lane = tid & 31;
    const int wid  = tid >> 5;
    const int wm   = wid >> 2;
    const int wn   = wid & 3;
    const int i0   = blockIdx.x * CTA_M;

    const int pr = tid >> 2;            // P-gen row 0..63
    const int kq = (tid & 3) * 8;       // 8 j's

    const float2 rt = g_RT[i0 + pr];
    const float Ri = rt.x, Ti = rt.y;
    float zacc = 0.f;

    float acc[2][8][4];
#pragma unroll
    for (int mt = 0; mt < 2; mt++)
#pragma unroll
        for (int nt = 0; nt < 8; nt++)
#pragma unroll
            for (int q = 0; q < 4; q++) acc[mt][nt][q] = 0.f;

    // ldmatrix source addresses (fixed per thread; buffer/k0 offsets added later)
    const uint32_t aAddrBase = smem_u32(&A_s[wm * 32 + (lane & 15)][(lane >> 4) * 8]);
    const uint32_t bAddrBase = smem_u32(&B_s[0][wn * 64 + (lane & 15)][(lane >> 4) * 8]);

    // prologue: cp.async B[0] + EFG[0]; adj regs chunk 0
    {
        uint32_t bdst = smem_u32(&B_s[0][tid][0]);
        const __half* bsrc = g_hT16 + (size_t)tid * NN;
#pragma unroll
        for (int q = 0; q < 4; q++) cp16(bdst + 16 * q, bsrc + 8 * q);
        if (tid < CH) cp16(smem_u32(&EFG_s[0][tid]), &g_EFG[tid]);
        cp_commit();
    }
    const int4* arow = reinterpret_cast<const int4*>(adj + (size_t)(i0 + pr) * NN);
    int4 av0 = arow[kq >> 2];
    int4 av1 = arow[(kq >> 2) + 1];

    for (int c = 0; c < NCH; c++) {
        const int cur = c & 1;

        cp_wait_all();
        __syncthreads();   // B[cur]/EFG[cur] visible; prev mma done (A_s reusable)

        // ---- P-gen into A_s ----
        {
            const float4* eb = EFG_s[cur];
            int avv[8] = {av0.x, av0.y, av0.z, av0.w, av1.x, av1.y, av1.z, av1.w};
            __half2 hp[4];
#pragma unroll
            for (int u = 0; u < 8; u += 2) {
                float4 e0 = eb[kq + u], e1 = eb[kq + u + 1];
                float p0 = (e0.z > Ti) ? e0.x : Ri * e0.y;
                float p1 = (e1.z > Ti) ? e1.x : Ri * e1.y;
                p0 = (avv[u] > 0) ? p0 : 0.f;
                p1 = (avv[u + 1] > 0) ? p1 : 0.f;
                zacc += p0 + p1;
                hp[u >> 1] = __floats2half2_rn(p0, p1);
            }
            *reinterpret_cast<uint4*>(&A_s[pr][kq]) = *reinterpret_cast<uint4*>(hp);
        }

        // ---- issue next chunk's cp.async + adj prefetch ----
        if (c + 1 < NCH) {
            const int jn = (c + 1) * CH;
            uint32_t bdst = smem_u32(&B_s[cur ^ 1][tid][0]);
            const __half* bsrc = g_hT16 + (size_t)tid * NN + jn;
#pragma unroll
            for (int q = 0; q < 4; q++) cp16(bdst + 16 * q, bsrc + 8 * q);
            if (tid < CH) cp16(smem_u32(&EFG_s[cur ^ 1][tid]), &g_EFG[jn + tid]);
            const int ji = (jn + kq) >> 2;
            av0 = arow[ji];
            av1 = arow[ji + 1];
        }
        cp_commit();
        __syncthreads();   // A_s ready for mma

        // ---- mma phase ----
        const uint32_t bufOff = cur * (uint32_t)sizeof(__half) * FOUT * BSTRIDE;
#pragma unroll
        for (int ks = 0; ks < 2; ks++) {
            const uint32_t kOff = ks * 16 * (uint32_t)sizeof(__half);
            uint32_t af[2][4];
            ldsm4(af[0], aAddrBase + kOff);                                    // m 0-15 (wm slab)
            ldsm4(af[1], aAddrBase + kOff + 16 * BSTRIDE * sizeof(__half));    // m 16-31
            uint32_t bf[4][4];
#pragma unroll
            for (int np = 0; np < 4; np++)
                ldsm4(bf[np], bAddrBase + bufOff + kOff +
                              np * 16 * BSTRIDE * (uint32_t)sizeof(__half));
#pragma unroll
            for (int np = 0; np < 4; np++) {
#pragma unroll
                for (int mt = 0; mt < 2; mt++) {
                    mma16816(acc[mt][2 * np],     af[mt], bf[np][0], bf[np][2]);
                    mma16816(acc[mt][2 * np + 1], af[mt], bf[np][1], bf[np][3]);
                }
            }
        }
        __syncthreads();   // mma reads done before next P-gen overwrites A_s
    }

    // ---- row-sum reduction ----
    zs[tid] = zacc;
    __syncthreads();
    if (tid < CTA_M)
        rowZ[tid] = zs[4 * tid] + zs[4 * tid + 1] + zs[4 * tid + 2] + zs[4 * tid + 3];
    __syncthreads();

    // ---- epilogue: normalize + store ----
#pragma unroll
    for (int mt = 0; mt < 2; mt++) {
        const int rca = wm * 32 + mt * 16 + (lane >> 2);
        const float inv0 = 1.0f / rowZ[rca];
        const float inv1 = 1.0f / rowZ[rca + 8];
        float* o0 = out + (size_t)(i0 + rca) * FOUT;
        float* o1 = out + (size_t)(i0 + rca + 8) * FOUT;
#pragma unroll
        for (int nt = 0; nt < 8; nt++) {
            const int colb = wn * 64 + nt * 8 + 2 * (lane & 3);
            *reinterpret_cast<float2*>(o0 + colb) =
                make_float2(acc[mt][nt][0] * inv0, acc[mt][nt][1] * inv0);
            *reinterpret_cast<float2*>(o1 + colb) =
                make_float2(acc[mt][nt][2] * inv1, acc[mt][nt][3] * inv1);
        }
    }
}

// ---------------------------------------------------------------------------
extern "C" void kernel_launch(void* const* d_in, const int* in_sizes, int n_in,
                              void* d_out, int out_size) {
    const float* x   = (const float*)d_in[0];
    const int*   adj = (const int*)  d_in[1];
    const float* W   = (const float*)d_in[2];
    const float* a   = (const float*)d_in[3];
    float* out = (float*)d_out;

    k_xw<<<NN / 32, 256>>>(x, W);
    k_scores<<<NN / 8, 256>>>(a);
    k_attn_f16<<<NN / CTA_M, 256>>>(adj, out);
}

// round 6
// speedup vs baseline: 2.8876x; 1.1850x over previous
#include <cuda_runtime.h>
#include <cuda_fp16.h>
#include <cstdint>

#define NN 8192
#define FIN 512
#define FOUT 256
#define CH 32
#define CTA_M 64
#define JHALF (NN / 2)
#define NCH_H (JHALF / CH)      // 128 chunks per half
#define BSTRIDE 40              // halves per row (80B): conflict-free ldmatrix

// ---------------- scratch (device globals; no allocation allowed) -----------
__device__ float   g_h   [(size_t)NN * FOUT];   // h = x@W fp32 (scores)
__device__ __half  g_hT16[(size_t)FOUT * NN];   // h^T fp16 (MMA B operand)
__device__ float4  g_EFG[NN];                   // per-j: (E, F, G, 0)
__device__ float2  g_RT [NN];                   // per-i: (R=e^{-0.8f}, T=-f)
__device__ float   g_S[2][(size_t)NN * FOUT];   // partial numerators per j-half
__device__ float   g_Z[2][NN];                  // partial row sums per j-half

// ---------------- helpers ----------------------------------------------------
static __device__ __forceinline__ float2 ffma2(float2 a, float2 b, float2 c) {
    unsigned long long A = *reinterpret_cast<unsigned long long*>(&a);
    unsigned long long B = *reinterpret_cast<unsigned long long*>(&b);
    unsigned long long C = *reinterpret_cast<unsigned long long*>(&c);
    unsigned long long D;
    asm("fma.rn.f32x2 %0, %1, %2, %3;" : "=l"(D) : "l"(A), "l"(B), "l"(C));
    return *reinterpret_cast<float2*>(&D);
}

static __device__ __forceinline__ uint32_t smem_u32(const void* p) {
    uint32_t a;
    asm("{ .reg .u64 t; cvta.to.shared.u64 t, %1; cvt.u32.u64 %0, t; }" : "=r"(a) : "l"(p));
    return a;
}

static __device__ __forceinline__ void cp16(uint32_t dst, const void* src) {
    asm volatile("cp.async.ca.shared.global [%0], [%1], 16;" :: "r"(dst), "l"(src));
}
static __device__ __forceinline__ void cp_commit() {
    asm volatile("cp.async.commit_group;");
}
static __device__ __forceinline__ void cp_wait_all() {
    asm volatile("cp.async.wait_group 0;");
}

static __device__ __forceinline__ void ldsm4(uint32_t* r, uint32_t addr) {
    asm volatile("ldmatrix.sync.aligned.m8n8.x4.shared.b16 {%0,%1,%2,%3}, [%4];"
                 : "=r"(r[0]), "=r"(r[1]), "=r"(r[2]), "=r"(r[3]) : "r"(addr));
}

static __device__ __forceinline__ void mma16816(float* d, const uint32_t* a,
                                                uint32_t b0, uint32_t b1) {
    asm volatile(
        "mma.sync.aligned.m16n8k16.row.col.f32.f16.f16.f32 "
        "{%0,%1,%2,%3}, {%4,%5,%6,%7}, {%8,%9}, {%0,%1,%2,%3};"
        : "+f"(d[0]), "+f"(d[1]), "+f"(d[2]), "+f"(d[3])
        : "r"(a[0]), "r"(a[1]), "r"(a[2]), "r"(a[3]), "r"(b0), "r"(b1));
}

// ---------------------------------------------------------------------------
// Kernel 1: h = x @ W (fp32 f32x2), x-tile prefetch pipelined, W unroll 8.
// ---------------------------------------------------------------------------
__global__ void __launch_bounds__(256) k_xw(const float* __restrict__ x,
                                            const float* __restrict__ W) {
    __shared__ __align__(16) float x_s[64][36];
    const int tid = threadIdx.x;
    const int i0  = blockIdx.x * 32;
    const int c   = tid;
    const int r   = tid >> 3;
    const int kq  = (tid & 7) * 8;

    float2 acc[16];
#pragma unroll
    for (int q = 0; q < 16; q++) acc[q] = make_float2(0.f, 0.f);

    // prefetch tile 0
    float4 v0 = *reinterpret_cast<const float4*>(&x[(i0 + r) * FIN + kq]);
    float4 v1 = *reinterpret_cast<const float4*>(&x[(i0 + r) * FIN + kq + 4]);

    for (int k0 = 0; k0 < FIN; k0 += 64) {
        __syncthreads();
        x_s[kq + 0][r] = v0.x; x_s[kq + 1][r] = v0.y;
        x_s[kq + 2][r] = v0.z; x_s[kq + 3][r] = v0.w;
        x_s[kq + 4][r] = v1.x; x_s[kq + 5][r] = v1.y;
        x_s[kq + 6][r] = v1.z; x_s[kq + 7][r] = v1.w;
        __syncthreads();

        if (k0 + 64 < FIN) {   // prefetch next tile (overlaps FMA below)
            v0 = *reinterpret_cast<const float4*>(&x[(i0 + r) * FIN + k0 + 64 + kq]);
            v1 = *reinterpret_cast<const float4*>(&x[(i0 + r) * FIN + k0 + 64 + kq + 4]);
        }

        const float* wp = W + k0 * FOUT + c;
#pragma unroll 8
        for (int kk = 0; kk < 64; kk++) {
            float wv = wp[kk * FOUT];
            float2 wv2 = make_float2(wv, wv);
#pragma unroll
            for (int q = 0; q < 8; q++) {
                float4 pq = *reinterpret_cast<const float4*>(&x_s[kk][q * 4]);
                acc[2 * q]     = ffma2(make_float2(pq.x, pq.y), wv2, acc[2 * q]);
                acc[2 * q + 1] = ffma2(make_float2(pq.z, pq.w), wv2, acc[2 * q + 1]);
            }
        }
    }
    float rv[32];
#pragma unroll
    for (int q = 0; q < 16; q++) {
        g_h[(size_t)(i0 + 2 * q) * FOUT + c]     = acc[q].x;
        g_h[(size_t)(i0 + 2 * q + 1) * FOUT + c] = acc[q].y;
        rv[2 * q] = acc[q].x; rv[2 * q + 1] = acc[q].y;
    }
    __half* ht = g_hT16 + (size_t)c * NN + i0;
#pragma unroll
    for (int q = 0; q < 4; q++) {
        __half2 h2[4];
#pragma unroll
        for (int u = 0; u < 4; u++)
            h2[u] = __floats2half2_rn(rv[8 * q + 2 * u], rv[8 * q + 2 * u + 1]);
        *reinterpret_cast<uint4*>(ht + 8 * q) = *reinterpret_cast<uint4*>(h2);
    }
}

// ---------------------------------------------------------------------------
// Kernel 2: per-node scores -> exp factors (O(N) exps total).
// ---------------------------------------------------------------------------
__global__ void __launch_bounds__(256) k_scores(const float* __restrict__ a) {
    const int w    = threadIdx.x >> 5;
    const int lane = threadIdx.x & 31;
    const int i    = blockIdx.x * 8 + w;

    float f = 0.f, g = 0.f;
#pragma unroll
    for (int q = 0; q < 8; q++) {
        int cidx = lane + q * 32;
        float hv = g_h[(size_t)i * FOUT + cidx];
        f += hv * a[cidx];
        g += hv * a[FOUT + cidx];
    }
#pragma unroll
    for (int off = 16; off; off >>= 1) {
        f += __shfl_down_sync(0xffffffffu, f, off);
        g += __shfl_down_sync(0xffffffffu, g, off);
    }
    if (lane == 0) {
        g_EFG[i] = make_float4(expf(g), expf(0.2f * g), g, 0.f);
        g_RT[i]  = make_float2(expf(-0.8f * f), -f);
    }
}

// ---------------------------------------------------------------------------
// Kernel 3: fp16 mma fused masked-softmax aggregation, j-SPLIT (2 CTAs/row-block).
// bid = rb*2 + half. Each CTA covers j in [half*4096, half*4096+4096).
// Writes unnormalized partials g_S[half], g_Z[half]. 2 CTAs/SM overlap phases.
// ---------------------------------------------------------------------------
__global__ void __launch_bounds__(256, 2) k_attn_f16(const int* __restrict__ adj) {
    __shared__ __align__(16) __half A_s[CTA_M][BSTRIDE];
    __shared__ __align__(16) __half B_s[2][FOUT][BSTRIDE];
    __shared__ __align__(16) float4 EFG_s[2][CH];
    __shared__ float zs[256];
    __shared__ float rowZ[CTA_M];

    const int tid  = threadIdx.x;
    const int lane = tid & 31;
    const int wid  = tid >> 5;
    const int wm   = wid >> 2;
    const int wn   = wid & 3;
    const int rb   = blockIdx.x >> 1;
    const int half = blockIdx.x & 1;
    const int i0   = rb * CTA_M;
    const int jb   = half * JHALF;

    const int pr = tid >> 2;
    const int kq = (tid & 3) * 8;

    const float2 rt = g_RT[i0 + pr];
    const float Ri = rt.x, Ti = rt.y;
    float zacc = 0.f;

    float acc[2][8][4];
#pragma unroll
    for (int mt = 0; mt < 2; mt++)
#pragma unroll
        for (int nt = 0; nt < 8; nt++)
#pragma unroll
            for (int q = 0; q < 4; q++) acc[mt][nt][q] = 0.f;

    const uint32_t aAddrBase = smem_u32(&A_s[wm * 32 + (lane & 15)][(lane >> 4) * 8]);
    const uint32_t bAddrBase = smem_u32(&B_s[0][wn * 64 + (lane & 15)][(lane >> 4) * 8]);

    // prologue
    {
        uint32_t bdst = smem_u32(&B_s[0][tid][0]);
        const __half* bsrc = g_hT16 + (size_t)tid * NN + jb;
#pragma unroll
        for (int q = 0; q < 4; q++) cp16(bdst + 16 * q, bsrc + 8 * q);
        if (tid < CH) cp16(smem_u32(&EFG_s[0][tid]), &g_EFG[jb + tid]);
        cp_commit();
    }
    const int4* arow = reinterpret_cast<const int4*>(adj + (size_t)(i0 + pr) * NN + jb);
    int4 av0 = arow[kq >> 2];
    int4 av1 = arow[(kq >> 2) + 1];

    for (int c = 0; c < NCH_H; c++) {
        const int cur = c & 1;

        cp_wait_all();
        __syncthreads();

        // ---- P-gen ----
        {
            const float4* eb = EFG_s[cur];
            int avv[8] = {av0.x, av0.y, av0.z, av0.w, av1.x, av1.y, av1.z, av1.w};
            __half2 hp[4];
#pragma unroll
            for (int u = 0; u < 8; u += 2) {
                float4 e0 = eb[kq + u], e1 = eb[kq + u + 1];
                float p0 = (e0.z > Ti) ? e0.x : Ri * e0.y;
                float p1 = (e1.z > Ti) ? e1.x : Ri * e1.y;
                p0 = (avv[u] > 0) ? p0 : 0.f;
                p1 = (avv[u + 1] > 0) ? p1 : 0.f;
                zacc += p0 + p1;
                hp[u >> 1] = __floats2half2_rn(p0, p1);
            }
            *reinterpret_cast<uint4*>(&A_s[pr][kq]) = *reinterpret_cast<uint4*>(hp);
        }

        // ---- next chunk staging ----
        if (c + 1 < NCH_H) {
            const int jn = (c + 1) * CH;
            uint32_t bdst = smem_u32(&B_s[cur ^ 1][tid][0]);
            const __half* bsrc = g_hT16 + (size_t)tid * NN + jb + jn;
#pragma unroll
            for (int q = 0; q < 4; q++) cp16(bdst + 16 * q, bsrc + 8 * q);
            if (tid < CH) cp16(smem_u32(&EFG_s[cur ^ 1][tid]), &g_EFG[jb + jn + tid]);
            const int ji = (jn + kq) >> 2;
            av0 = arow[ji];
            av1 = arow[ji + 1];
        }
        cp_commit();
        __syncthreads();

        // ---- mma ----
        const uint32_t bufOff = cur * (uint32_t)sizeof(__half) * FOUT * BSTRIDE;
#pragma unroll
        for (int ks = 0; ks < 2; ks++) {
            const uint32_t kOff = ks * 16 * (uint32_t)sizeof(__half);
            uint32_t af[2][4];
            ldsm4(af[0], aAddrBase + kOff);
            ldsm4(af[1], aAddrBase + kOff + 16 * BSTRIDE * sizeof(__half));
            uint32_t bf[4][4];
#pragma unroll
            for (int np = 0; np < 4; np++)
                ldsm4(bf[np], bAddrBase + bufOff + kOff +
                              np * 16 * BSTRIDE * (uint32_t)sizeof(__half));
#pragma unroll
            for (int np = 0; np < 4; np++) {
#pragma unroll
                for (int mt = 0; mt < 2; mt++) {
                    mma16816(acc[mt][2 * np],     af[mt], bf[np][0], bf[np][2]);
                    mma16816(acc[mt][2 * np + 1], af[mt], bf[np][1], bf[np][3]);
                }
            }
        }
        __syncthreads();
    }

    // ---- partial row sums ----
    zs[tid] = zacc;
    __syncthreads();
    if (tid < CTA_M) {
        float z = zs[4 * tid] + zs[4 * tid + 1] + zs[4 * tid + 2] + zs[4 * tid + 3];
        rowZ[tid] = z;
        g_Z[half][i0 + tid] = z;
    }
    __syncthreads();

    // ---- store unnormalized partials ----
    float* Sp = g_S[half];
#pragma unroll
    for (int mt = 0; mt < 2; mt++) {
        const int rca = wm * 32 + mt * 16 + (lane >> 2);
        float* o0 = Sp + (size_t)(i0 + rca) * FOUT;
        float* o1 = Sp + (size_t)(i0 + rca + 8) * FOUT;
#pragma unroll
        for (int nt = 0; nt < 8; nt++) {
            const int colb = wn * 64 + nt * 8 + 2 * (lane & 3);
            *reinterpret_cast<float2*>(o0 + colb) = make_float2(acc[mt][nt][0], acc[mt][nt][1]);
            *reinterpret_cast<float2*>(o1 + colb) = make_float2(acc[mt][nt][2], acc[mt][nt][3]);
        }
    }
}

// ---------------------------------------------------------------------------
// Kernel 4: combine halves: out = (S0+S1) / (Z0+Z1)
// ---------------------------------------------------------------------------
__global__ void __launch_bounds__(256) k_combine(float* __restrict__ out) {
    const int i = blockIdx.x;
    const int c = threadIdx.x;
    const float inv = 1.0f / (g_Z[0][i] + g_Z[1][i]);
    const size_t idx = (size_t)i * FOUT + c;
    out[idx] = (g_S[0][idx] + g_S[1][idx]) * inv;
}

// ---------------------------------------------------------------------------
extern "C" void kernel_launch(void* const* d_in, const int* in_sizes, int n_in,
                              void* d_out, int out_size) {
    const float* x   = (const float*)d_in[0];
    const int*   adj = (const int*)  d_in[1];
    const float* W   = (const float*)d_in[2];
    const float* a   = (const float*)d_in[3];
    float* out = (float*)d_out;

    k_xw<<<NN / 32, 256>>>(x, W);
    k_scores<<<NN / 8, 256>>>(a);
    k_attn_f16<<<(NN / CTA_M) * 2, 256>>>(adj);
    k_combine<<<NN, 256>>>(out);
}